// round 12
// baseline (speedup 1.0000x reference)
#include <cuda_runtime.h>
#include <cuda_bf16.h>
#include <stdint.h>

#define S_LEN 4096
#define NB    16
#define TILE_U (16 * 64 * 512)    // (b, tile) -> 512 uint4 per tile

// Pre-converted, pre-swizzled bf16 hi/lo K and V tiles (8 MB each, 32 MB total).
static __device__ uint4 g_kh[TILE_U], g_kl[TILE_U], g_vh[TILE_U], g_vl[TILE_U];

// ---------------------------------------------------------------------------
// threefry2x32, key=(0,1), counter (0,i), partitionable stream (validated).
// R7 asm form (known-good 1081us baseline).
// ---------------------------------------------------------------------------
__device__ __forceinline__ uint32_t tf_bits(uint32_t i, uint32_t one) {
#define TFR(r) { asm("mad.lo.u32 %0, %1, %2, %0;" : "+r"(x0) : "r"(x1), "r"(one)); \
                 x1 = __funnelshift_l(x1, x1, (r)) ^ x0; }
#define KADD(v, C) asm("mad.lo.u32 %0, %1, %2, %0;" : "+r"(v) : "r"(one), "n"(C))
    uint32_t x1 = i + 1u;                 // inject 0: x1 += ks1 (x0 += 0)
    uint32_t x0 = x1;                     // round 1 specialized (x0 was 0)
    x1 = __funnelshift_l(x1, x1, 13) ^ x0;
    TFR(15) TFR(26) TFR(6)
    KADD(x0, 1);           KADD(x1, 0x1BD11BDC);   // inject 1
    TFR(17) TFR(29) TFR(16) TFR(24)
    KADD(x0, 0x1BD11BDB);  KADD(x1, 2);            // inject 2
    TFR(13) TFR(15) TFR(26) TFR(6)
    KADD(x1, 4);                                   // inject 3 (x0 += 0)
    TFR(17) TFR(29) TFR(16) TFR(24)
    KADD(x0, 1);           KADD(x1, 0x1BD11BDF);   // inject 4
    TFR(13) TFR(15) TFR(26) TFR(6)
    KADD(x0, 0x1BD11BDB);  KADD(x1, 5);            // inject 5
    return x0 ^ x1;
#undef TFR
#undef KADD
}

// ---------------------------------------------------------------------------
__device__ __forceinline__ uint32_t smem_u32(const void* p) {
    uint32_t a;
    asm("{ .reg .u64 t; cvta.to.shared.u64 t, %1; cvt.u32.u64 %0, t; }" : "=r"(a) : "l"(p));
    return a;
}
__device__ __forceinline__ uint32_t pack_bf(float a, float b) {
    __nv_bfloat162 t = __floats2bfloat162_rn(a, b);
    return *(uint32_t*)&t;
}
__device__ __forceinline__ void split2(float a, float b, uint32_t& hi, uint32_t& lo) {
    float ha = __bfloat162float(__float2bfloat16(a));
    float hb = __bfloat162float(__float2bfloat16(b));
    hi = pack_bf(ha, hb);
    lo = pack_bf(a - ha, b - hb);
}
__device__ __forceinline__ void ldsm2(uint32_t& r0, uint32_t& r1, uint32_t a) {
    asm volatile("ldmatrix.sync.aligned.m8n8.x2.shared.b16 {%0,%1}, [%2];"
                 : "=r"(r0), "=r"(r1) : "r"(a));
}
__device__ __forceinline__ void ldsm2t(uint32_t& r0, uint32_t& r1, uint32_t a) {
    asm volatile("ldmatrix.sync.aligned.m8n8.x2.trans.shared.b16 {%0,%1}, [%2];"
                 : "=r"(r0), "=r"(r1) : "r"(a));
}
__device__ __forceinline__ void mma_bf16(float* d, const uint32_t* a, uint32_t b0, uint32_t b1) {
    asm volatile(
        "mma.sync.aligned.m16n8k16.row.col.f32.bf16.bf16.f32 "
        "{%0,%1,%2,%3}, {%4,%5,%6,%7}, {%8,%9}, {%0,%1,%2,%3};"
        : "+f"(d[0]), "+f"(d[1]), "+f"(d[2]), "+f"(d[3])
        : "r"(a[0]), "r"(a[1]), "r"(a[2]), "r"(a[3]), "r"(b0), "r"(b1));
}
__device__ __forceinline__ void cpa16(uint32_t dst, const void* src) {
    asm volatile("cp.async.cg.shared.global [%0], [%1], 16;" :: "r"(dst), "l"(src) : "memory");
}
#define CP_COMMIT() asm volatile("cp.async.commit_group;" ::: "memory")
#define CP_WAIT0()  asm volatile("cp.async.wait_group 0;" ::: "memory")

// ---------------------------------------------------------------------------
// Prepass: K,V fp32 -> bf16 hi/lo tiles in smem-swizzled order.
// ---------------------------------------------------------------------------
__global__ void __launch_bounds__(256) prep_kv(const float* __restrict__ K,
                                               const float* __restrict__ V) {
    uint32_t idx = blockIdx.x * 256u + threadIdx.x;   // (b<<15)|(s<<3)|c16
    uint32_t c16 = idx & 7u, s = (idx >> 3) & 4095u, b = idx >> 15;
    uint32_t row = s & 63u, tile = s >> 6;
    uint32_t sidx = row * 8u + (c16 ^ (row & 7u));
    size_t dst = ((size_t)(b * 64u + tile)) * 512u + sidx;
    size_t src = ((size_t)(b * 4096u + s)) * 64u + c16 * 8u;
    {
        const float4* p = (const float4*)(K + src);
        float4 a0 = p[0], a1 = p[1];
        uint4 h, l;
        split2(a0.x, a0.y, h.x, l.x); split2(a0.z, a0.w, h.y, l.y);
        split2(a1.x, a1.y, h.z, l.z); split2(a1.z, a1.w, h.w, l.w);
        g_kh[dst] = h; g_kl[dst] = l;
    }
    {
        const float4* p = (const float4*)(V + src);
        float4 a0 = p[0], a1 = p[1];
        uint4 h, l;
        split2(a0.x, a0.y, h.x, l.x); split2(a0.z, a0.w, h.y, l.y);
        split2(a1.x, a1.y, h.z, l.z); split2(a1.z, a1.w, h.w, l.w);
        g_vh[dst] = h; g_vl[dst] = l;
    }
}

// ---------------------------------------------------------------------------
// Fused flash attention + threefry dropout (R7 body; RNG groups 4..7
// interleaved into the QK MMA loop to fill ldsm/mma dependency stalls).
// 128 threads/CTA, 3 CTAs/SM; bf16x3 emulation (lo*lo dropped, ~1.6e-5).
// ---------------------------------------------------------------------------
__global__ void __launch_bounds__(128, 3) fused_attn(
    const float* __restrict__ Q, const float* __restrict__ pd,
    const float* __restrict__ isf, float* __restrict__ Og)
{
    __shared__ uint4 KhS[512], KlS[512], VhS[512], VlS[512];

    const int tid = threadIdx.x;
    const int w = tid >> 5, lane = tid & 31;
    const int g = lane >> 2, tg = lane & 3;
    const int b = blockIdx.y, qt = blockIdx.x;

    const float rscale = 1.0f / (*isf);
    const float keep_p = 1.0f - *pd;
    const float inv_keep = 1.0f / keep_p;
    const uint32_t T = (uint32_t)ceilf(keep_p * 8388608.0f);
    const uint64_t T9w = ((uint64_t)T) << 9;
    const uint32_t T9 = T9w > 0xFFFFFFFFull ? 0xFFFFFFFFu : (uint32_t)T9w;
    const uint32_t one = (T >> 31) | 1u;               // opaque 1

    const uint32_t kh_b = smem_u32(KhS), kl_b = smem_u32(KlS);
    const uint32_t vh_b = smem_u32(VhS), vl_b = smem_u32(VlS);

    const int li = lane & 15;      // ldmatrix address lane
    const int lr = li & 7;         // row-within-8
    const int lh = li >> 3;        // matrix half

    const int qr0 = b * S_LEN + qt * 64 + w * 16 + g;   // global q row (g)
    const int qr1 = qr0 + 8;                            // row g+8

    // ---- Q A-fragments (hi/lo), 4 k16-steps, register-resident ----
    uint32_t qh[4][4], ql[4][4];
#pragma unroll
    for (int kk = 0; kk < 4; ++kk) {
        int c = kk * 16 + 2 * tg;
        float2 f0 = *(const float2*)(Q + (size_t)qr0 * 64 + c);
        float2 f1 = *(const float2*)(Q + (size_t)qr1 * 64 + c);
        float2 f2 = *(const float2*)(Q + (size_t)qr0 * 64 + c + 8);
        float2 f3 = *(const float2*)(Q + (size_t)qr1 * 64 + c + 8);
        split2(f0.x * rscale, f0.y * rscale, qh[kk][0], ql[kk][0]);
        split2(f1.x * rscale, f1.y * rscale, qh[kk][1], ql[kk][1]);
        split2(f2.x * rscale, f2.y * rscale, qh[kk][2], ql[kk][2]);
        split2(f3.x * rscale, f3.y * rscale, qh[kk][3], ql[kk][3]);
    }

    float o[8][4];
#pragma unroll
    for (int v = 0; v < 8; ++v)
#pragma unroll
        for (int i = 0; i < 4; ++i) o[v][i] = 0.f;
    float lsum0 = 0.f, lsum1 = 0.f;

    const uint32_t r0f = (uint32_t)qr0 * (uint32_t)S_LEN;
    const uint32_t r1f = (uint32_t)qr1 * (uint32_t)S_LEN;

    for (int kt = 0; kt < 64; ++kt) {
        __syncthreads();       // prior tile's reads complete

        // ---- stage pre-converted K/V tile via cp.async ----
        const size_t tb = ((size_t)(b * 64 + kt)) * 512;
        const uint4* pKh = g_kh + tb;
        const uint4* pKl = g_kl + tb;
        const uint4* pVh = g_vh + tb;
        const uint4* pVl = g_vl + tb;
#pragma unroll
        for (int u = 0; u < 4; ++u) {
            int i = tid + u * 128;
            cpa16(kh_b + i * 16, pKh + i);
            cpa16(kl_b + i * 16, pKl + i);
            cpa16(vh_b + i * 16, pVh + i);
            cpa16(vl_b + i * 16, pVl + i);
        }
        CP_COMMIT();

        const uint32_t cbase = (uint32_t)(kt * 64 + 2 * tg);

        // ---- threefry groups 0..3 upfront (overlaps cp.async latency) ----
        uint32_t mb;
        {
            uint32_t f0 = r0f + cbase + 24u;   // group 3 base, descending
            uint32_t f1 = r1f + cbase + 24u;
            mb = 0u;
#pragma unroll 2
            for (int t = 0; t < 4; ++t) {
                uint32_t k0 = tf_bits(f0,      one) < T9 ? 1u : 0u;
                uint32_t k1 = tf_bits(f0 + 1u, one) < T9 ? 1u : 0u;
                uint32_t k2 = tf_bits(f1,      one) < T9 ? 1u : 0u;
                uint32_t k3 = tf_bits(f1 + 1u, one) < T9 ? 1u : 0u;
                uint32_t b01, b23;
                asm("mad.lo.u32 %0, %1, 2, %2;"  : "=r"(b01) : "r"(k1),  "r"(k0));
                asm("mad.lo.u32 %0, %1, 2, %2;"  : "=r"(b23) : "r"(k3),  "r"(k2));
                asm("mad.lo.u32 %0, %1, 4, %2;"  : "=r"(b01) : "r"(b23), "r"(b01));
                asm("mad.lo.u32 %0, %1, 16, %2;" : "=r"(mb)  : "r"(mb),  "r"(b01));
                f0 -= 8u; f1 -= 8u;
            }
        }

        CP_WAIT0();
        __syncthreads();

        // ---- S = Q K^T, with threefry groups 4..7 interleaved ----
        float s[8][4];
#pragma unroll
        for (int t = 0; t < 8; ++t) {
#pragma unroll
            for (int i = 0; i < 4; ++i) s[t][i] = 0.f;

            if (t >= 4) {   // RNG group t: alu work fills ldsm/mma stalls
                uint32_t f0 = r0f + cbase + (uint32_t)(t * 8);
                uint32_t f1 = r1f + cbase + (uint32_t)(t * 8);
                uint32_t k0 = tf_bits(f0,      one) < T9 ? 1u : 0u;
                uint32_t k1 = tf_bits(f0 + 1u, one) < T9 ? 1u : 0u;
                uint32_t k2 = tf_bits(f1,      one) < T9 ? 1u : 0u;
                uint32_t k3 = tf_bits(f1 + 1u, one) < T9 ? 1u : 0u;
                mb |= (k0 | (k1 << 1) | (k2 << 2) | (k3 << 3)) << (4 * t);
            }
#pragma unroll
            for (int kk = 0; kk < 4; ++kk) {
                uint32_t off = (uint32_t)(t * 64 + lr * 8 + ((kk * 2 + lh) ^ lr)) * 16;
                uint32_t bh0, bh1, bl0, bl1;
                ldsm2(bh0, bh1, kh_b + off);
                ldsm2(bl0, bl1, kl_b + off);
                mma_bf16(s[t], qh[kk], bh0, bh1);
                mma_bf16(s[t], ql[kk], bh0, bh1);
                mma_bf16(s[t], qh[kk], bl0, bl1);
            }
        }

        // ---- softmax (no max shift), dropout, pack P A-frags ----
        uint32_t ph[4][4], pl[4][4];
#pragma unroll
        for (int t = 0; t < 8; ++t) {
            float p0 = __expf(s[t][0]);
            float p1 = __expf(s[t][1]);
            float p2 = __expf(s[t][2]);
            float p3 = __expf(s[t][3]);
            lsum0 += p0 + p1;            // denominator: un-dropped probs
            lsum1 += p2 + p3;
            uint32_t m4 = mb >> (4 * t);
            float d0 = (m4 & 1u) ? p0 : 0.f;
            float d1 = (m4 & 2u) ? p1 : 0.f;
            float d2 = (m4 & 4u) ? p2 : 0.f;
            float d3 = (m4 & 8u) ? p3 : 0.f;
            int j = t >> 1, a = (t & 1) * 2;
            split2(d0, d1, ph[j][a],     pl[j][a]);       // row g
            split2(d2, d3, ph[j][a + 1], pl[j][a + 1]);   // row g+8
        }

        // ---- O += P V ----
#pragma unroll
        for (int j = 0; j < 4; ++j) {
#pragma unroll
            for (int v = 0; v < 8; ++v) {
                uint32_t off = (uint32_t)((j * 16 + li) * 8 + (v ^ lr)) * 16;
                uint32_t bh0, bh1, bl0, bl1;
                ldsm2t(bh0, bh1, vh_b + off);
                ldsm2t(bl0, bl1, vl_b + off);
                mma_bf16(o[v], ph[j], bh0, bh1);
                mma_bf16(o[v], pl[j], bh0, bh1);
                mma_bf16(o[v], ph[j], bl0, bl1);
            }
        }
    }

    // ---- epilogue: quad-reduce l, scale, store ----
    lsum0 += __shfl_xor_sync(0xffffffffu, lsum0, 1);
    lsum0 += __shfl_xor_sync(0xffffffffu, lsum0, 2);
    lsum1 += __shfl_xor_sync(0xffffffffu, lsum1, 1);
    lsum1 += __shfl_xor_sync(0xffffffffu, lsum1, 2);
    const float sc0 = inv_keep / lsum0;
    const float sc1 = inv_keep / lsum1;
#pragma unroll
    for (int v = 0; v < 8; ++v) {
        int c = v * 8 + 2 * tg;
        *(float2*)(Og + (size_t)qr0 * 64 + c) = make_float2(o[v][0] * sc0, o[v][1] * sc0);
        *(float2*)(Og + (size_t)qr1 * 64 + c) = make_float2(o[v][2] * sc1, o[v][3] * sc1);
    }
}

extern "C" void kernel_launch(void* const* d_in, const int* in_sizes, int n_in,
                              void* d_out, int out_size) {
    (void)in_sizes; (void)n_in; (void)out_size;
    const float* Q = (const float*)d_in[0];
    const float* K = (const float*)d_in[1];
    const float* V = (const float*)d_in[2];
    prep_kv<<<2048, 256>>>(K, V);
    fused_attn<<<dim3(S_LEN / 64, NB), 128>>>(
        Q, (const float*)d_in[3], (const float*)d_in[4], (float*)d_out);
}

// round 13
// speedup vs baseline: 1.0363x; 1.0363x over previous
#include <cuda_runtime.h>
#include <cuda_bf16.h>
#include <stdint.h>

#define S_LEN 4096
#define NB    16
#define TILE_U (16 * 64 * 512)    // (b, tile) -> 512 uint4 per tile

// Pre-converted, pre-swizzled bf16 hi/lo K and V tiles (8 MB each, 32 MB total).
static __device__ uint4 g_kh[TILE_U], g_kl[TILE_U], g_vh[TILE_U], g_vl[TILE_U];

// ---------------------------------------------------------------------------
// threefry2x32, key=(0,1), counter (0,i), partitionable stream (validated).
// Plain C: ptxas fuses injections into 3-input IADD3 and balances pipes.
// ---------------------------------------------------------------------------
__device__ __forceinline__ uint32_t tf_bits(uint32_t i) {
#define TFR(r) { x0 += x1; x1 = __funnelshift_l(x1, x1, (r)) ^ x0; }
    uint32_t x1 = i + 1u;                 // inject 0: x1 += ks1 (x0 += 0)
    uint32_t x0 = x1;                     // round 1 specialized (x0 was 0)
    x1 = __funnelshift_l(x1, x1, 13) ^ x0;
    TFR(15) TFR(26) TFR(6)
    x0 += 1u;           x1 += 0x1BD11BDCu;   // inject 1: ks1, ks2+1
    TFR(17) TFR(29) TFR(16) TFR(24)
    x0 += 0x1BD11BDBu;  x1 += 2u;            // inject 2: ks2, ks0+2
    TFR(13) TFR(15) TFR(26) TFR(6)
    x1 += 4u;                                // inject 3: ks0(=0), ks1+3
    TFR(17) TFR(29) TFR(16) TFR(24)
    x0 += 1u;           x1 += 0x1BD11BDFu;   // inject 4: ks1, ks2+4
    TFR(13) TFR(15) TFR(26) TFR(6)
    x0 += 0x1BD11BDBu;  x1 += 5u;            // inject 5: ks2, ks0+5
    return x0 ^ x1;
#undef TFR
}

// ---------------------------------------------------------------------------
__device__ __forceinline__ uint32_t smem_u32(const void* p) {
    uint32_t a;
    asm("{ .reg .u64 t; cvta.to.shared.u64 t, %1; cvt.u32.u64 %0, t; }" : "=r"(a) : "l"(p));
    return a;
}
__device__ __forceinline__ uint32_t pack_bf(float a, float b) {
    __nv_bfloat162 t = __floats2bfloat162_rn(a, b);
    return *(uint32_t*)&t;
}
__device__ __forceinline__ void split2(float a, float b, uint32_t& hi, uint32_t& lo) {
    float ha = __bfloat162float(__float2bfloat16(a));
    float hb = __bfloat162float(__float2bfloat16(b));
    hi = pack_bf(ha, hb);
    lo = pack_bf(a - ha, b - hb);
}
__device__ __forceinline__ void ldsm2(uint32_t& r0, uint32_t& r1, uint32_t a) {
    asm volatile("ldmatrix.sync.aligned.m8n8.x2.shared.b16 {%0,%1}, [%2];"
                 : "=r"(r0), "=r"(r1) : "r"(a));
}
__device__ __forceinline__ void ldsm2t(uint32_t& r0, uint32_t& r1, uint32_t a) {
    asm volatile("ldmatrix.sync.aligned.m8n8.x2.trans.shared.b16 {%0,%1}, [%2];"
                 : "=r"(r0), "=r"(r1) : "r"(a));
}
__device__ __forceinline__ void mma_bf16(float* d, const uint32_t* a, uint32_t b0, uint32_t b1) {
    asm volatile(
        "mma.sync.aligned.m16n8k16.row.col.f32.bf16.bf16.f32 "
        "{%0,%1,%2,%3}, {%4,%5,%6,%7}, {%8,%9}, {%0,%1,%2,%3};"
        : "+f"(d[0]), "+f"(d[1]), "+f"(d[2]), "+f"(d[3])
        : "r"(a[0]), "r"(a[1]), "r"(a[2]), "r"(a[3]), "r"(b0), "r"(b1));
}
__device__ __forceinline__ void cpa16(uint32_t dst, const void* src) {
    asm volatile("cp.async.cg.shared.global [%0], [%1], 16;" :: "r"(dst), "l"(src) : "memory");
}
__device__ __forceinline__ void sts32(uint32_t a, uint32_t v) {
    asm volatile("st.shared.b32 [%0], %1;" :: "r"(a), "r"(v) : "memory");
}
__device__ __forceinline__ uint32_t lds32(uint32_t a) {
    uint32_t v;
    asm volatile("ld.shared.b32 %0, [%1];" : "=r"(v) : "r"(a));
    return v;
}
#define CP_COMMIT() asm volatile("cp.async.commit_group;" ::: "memory")
#define CP_WAIT1()  asm volatile("cp.async.wait_group 1;" ::: "memory")
#define BAR1()      asm volatile("bar.sync 1, 128;" ::: "memory")

// ---------------------------------------------------------------------------
// Prepass: K,V fp32 -> bf16 hi/lo tiles in smem-swizzled order.
// ---------------------------------------------------------------------------
__global__ void __launch_bounds__(256) prep_kv(const float* __restrict__ K,
                                               const float* __restrict__ V) {
    uint32_t idx = blockIdx.x * 256u + threadIdx.x;   // (b<<15)|(s<<3)|c16
    uint32_t c16 = idx & 7u, s = (idx >> 3) & 4095u, b = idx >> 15;
    uint32_t row = s & 63u, tile = s >> 6;
    uint32_t sidx = row * 8u + (c16 ^ (row & 7u));
    size_t dst = ((size_t)(b * 64u + tile)) * 512u + sidx;
    size_t src = ((size_t)(b * 4096u + s)) * 64u + c16 * 8u;
    {
        const float4* p = (const float4*)(K + src);
        float4 a0 = p[0], a1 = p[1];
        uint4 h, l;
        split2(a0.x, a0.y, h.x, l.x); split2(a0.z, a0.w, h.y, l.y);
        split2(a1.x, a1.y, h.z, l.z); split2(a1.z, a1.w, h.w, l.w);
        g_kh[dst] = h; g_kl[dst] = l;
    }
    {
        const float4* p = (const float4*)(V + src);
        float4 a0 = p[0], a1 = p[1];
        uint4 h, l;
        split2(a0.x, a0.y, h.x, l.x); split2(a0.z, a0.w, h.y, l.y);
        split2(a1.x, a1.y, h.z, l.z); split2(a1.z, a1.w, h.w, l.w);
        g_vh[dst] = h; g_vl[dst] = l;
    }
}

// ---------------------------------------------------------------------------
// Warp-specialized fused flash attention + threefry dropout.
// 256 threads/CTA: warps 0-3 MMA (R11 halved body, FP order identical),
// warps 4-7 RNG (pure threefry, one tile ahead, double-buffered smem mask).
// K/V double-buffered via cp.async pipelined one tile ahead.
// bf16x3 emulation: hi*hi + lo*hi + hi*lo (lo*lo dropped, ~1.6e-5).
// ---------------------------------------------------------------------------
__global__ void __launch_bounds__(256, 2) fused_attn(
    const float* __restrict__ Q, const float* __restrict__ pd,
    const float* __restrict__ isf, float* __restrict__ Og)
{
    extern __shared__ __align__(16) uint4 dsm[];   // 65536 B K/V + 1024 B mask
    const uint32_t sb  = smem_u32(dsm);
    const uint32_t mkb = sb + 65536u;

    const int tid = threadIdx.x;
    const bool is_mma = tid < 128;
    const int mt = tid & 127;            // role-local index (maps RNG r -> MMA r)
    const int w = mt >> 5, lane = tid & 31;
    const int g = lane >> 2, tg = lane & 3;
    const int b = blockIdx.y, qt = blockIdx.x;

    const float rscale = 1.0f / (*isf);
    const float keep_p = 1.0f - *pd;
    const float inv_keep = 1.0f / keep_p;
    const uint32_t T = (uint32_t)ceilf(keep_p * 8388608.0f);
    const uint64_t T9w = ((uint64_t)T) << 9;
    const uint32_t T9 = T9w > 0xFFFFFFFFull ? 0xFFFFFFFFu : (uint32_t)T9w;

    const int li = lane & 15;      // ldmatrix address lane
    const int lr = li & 7;
    const int lh = li >> 3;

    const int qr0 = b * S_LEN + qt * 64 + w * 16 + g;   // global q row (g)
    const int qr1 = qr0 + 8;                            // row g+8
    const uint32_t r0f = (uint32_t)qr0 * (uint32_t)S_LEN;
    const uint32_t r1f = (uint32_t)qr1 * (uint32_t)S_LEN;

    uint32_t qh[4][4], ql[4][4];
    float o[8][4];
    float lsum0 = 0.f, lsum1 = 0.f;

    if (is_mma) {
        // ---- Q A-fragments (hi/lo), register-resident ----
#pragma unroll
        for (int kk = 0; kk < 4; ++kk) {
            int c = kk * 16 + 2 * tg;
            float2 f0 = *(const float2*)(Q + (size_t)qr0 * 64 + c);
            float2 f1 = *(const float2*)(Q + (size_t)qr1 * 64 + c);
            float2 f2 = *(const float2*)(Q + (size_t)qr0 * 64 + c + 8);
            float2 f3 = *(const float2*)(Q + (size_t)qr1 * 64 + c + 8);
            split2(f0.x * rscale, f0.y * rscale, qh[kk][0], ql[kk][0]);
            split2(f1.x * rscale, f1.y * rscale, qh[kk][1], ql[kk][1]);
            split2(f2.x * rscale, f2.y * rscale, qh[kk][2], ql[kk][2]);
            split2(f3.x * rscale, f3.y * rscale, qh[kk][3], ql[kk][3]);
        }
#pragma unroll
        for (int v = 0; v < 8; ++v)
#pragma unroll
            for (int i = 0; i < 4; ++i) o[v][i] = 0.f;

        // ---- stage tile 0 into buffer 0 ----
        const size_t tb = ((size_t)(b * 64)) * 512;
#pragma unroll
        for (int u = 0; u < 4; ++u) {
            int i = mt + u * 128;
            cpa16(sb + i * 16,         g_kh + tb + i);
            cpa16(sb + 8192 + i * 16,  g_kl + tb + i);
            cpa16(sb + 16384 + i * 16, g_vh + tb + i);
            cpa16(sb + 24576 + i * 16, g_vl + tb + i);
        }
        CP_COMMIT();
    } else {
        // ---- RNG prologue: mask for tile 0 ----
        uint32_t mbv = 0u;
        uint32_t f0 = r0f + (uint32_t)(2 * tg);
        uint32_t f1 = r1f + (uint32_t)(2 * tg);
#pragma unroll 2
        for (int t = 0; t < 8; ++t) {
            uint32_t k0 = tf_bits(f0)      < T9 ? 1u : 0u;
            uint32_t k1 = tf_bits(f0 + 1u) < T9 ? 1u : 0u;
            uint32_t k2 = tf_bits(f1)      < T9 ? 1u : 0u;
            uint32_t k3 = tf_bits(f1 + 1u) < T9 ? 1u : 0u;
            mbv |= (k0 | (k1 << 1) | (k2 << 2) | (k3 << 3)) << (4 * t);
            f0 += 8u; f1 += 8u;
        }
        sts32(mkb + mt * 4, mbv);
    }

    for (int kt = 0; kt < 64; ++kt) {
        __syncthreads();   // hand off mask[kt]; recycle K/V + mask buffers

        if (is_mma) {
            const uint32_t cur = sb + (uint32_t)(kt & 1) * 32768u;

            // ---- prefetch tile kt+1 into the idle buffer ----
            if (kt < 63) {
                const uint32_t nxt = sb + (uint32_t)((kt + 1) & 1) * 32768u;
                const size_t tb = ((size_t)(b * 64 + kt + 1)) * 512;
#pragma unroll
                for (int u = 0; u < 4; ++u) {
                    int i = mt + u * 128;
                    cpa16(nxt + i * 16,         g_kh + tb + i);
                    cpa16(nxt + 8192 + i * 16,  g_kl + tb + i);
                    cpa16(nxt + 16384 + i * 16, g_vh + tb + i);
                    cpa16(nxt + 24576 + i * 16, g_vl + tb + i);
                }
            }
            CP_COMMIT();           // (empty group at kt=63 keeps counts uniform)
            CP_WAIT1();            // tile kt resident for this thread
            BAR1();                // visible across the 4 MMA warps only

            const uint32_t mb = lds32(mkb + (uint32_t)(kt & 1) * 512u + mt * 4);
            const uint32_t kh_b = cur, kl_b = cur + 8192;
            const uint32_t vh_b = cur + 16384, vl_b = cur + 24576;

            // ---- two 32-column halves: QK -> softmax/dropout -> PV ----
#pragma unroll
            for (int h = 0; h < 2; ++h) {
                float s4[4][4];
#pragma unroll
                for (int t = 0; t < 4; ++t)
#pragma unroll
                    for (int i = 0; i < 4; ++i) s4[t][i] = 0.f;
#pragma unroll
                for (int t = 0; t < 4; ++t) {
                    const int tt = h * 4 + t;
#pragma unroll
                    for (int kk = 0; kk < 4; ++kk) {
                        uint32_t off = (uint32_t)(tt * 64 + lr * 8 + ((kk * 2 + lh) ^ lr)) * 16;
                        uint32_t bh0, bh1, bl0, bl1;
                        ldsm2(bh0, bh1, kh_b + off);
                        ldsm2(bl0, bl1, kl_b + off);
                        mma_bf16(s4[t], qh[kk], bh0, bh1);
                        mma_bf16(s4[t], ql[kk], bh0, bh1);
                        mma_bf16(s4[t], qh[kk], bl0, bl1);
                    }
                }

                uint32_t ph[2][4], pl[2][4];
#pragma unroll
                for (int t = 0; t < 4; ++t) {
                    const int tt = h * 4 + t;
                    float p0 = __expf(s4[t][0]);
                    float p1 = __expf(s4[t][1]);
                    float p2 = __expf(s4[t][2]);
                    float p3 = __expf(s4[t][3]);
                    lsum0 += p0 + p1;            // denominator: un-dropped probs
                    lsum1 += p2 + p3;
                    uint32_t m4 = mb >> (4 * tt);
                    float d0 = (m4 & 1u) ? p0 : 0.f;
                    float d1 = (m4 & 2u) ? p1 : 0.f;
                    float d2 = (m4 & 4u) ? p2 : 0.f;
                    float d3 = (m4 & 8u) ? p3 : 0.f;
                    int j = t >> 1, a = (t & 1) * 2;
                    split2(d0, d1, ph[j][a],     pl[j][a]);       // row g
                    split2(d2, d3, ph[j][a + 1], pl[j][a + 1]);   // row g+8
                }
#pragma unroll
                for (int j2 = 0; j2 < 2; ++j2) {
                    const int j = h * 2 + j2;
#pragma unroll
                    for (int v = 0; v < 8; ++v) {
                        uint32_t off = (uint32_t)((j * 16 + li) * 8 + (v ^ lr)) * 16;
                        uint32_t bh0, bh1, bl0, bl1;
                        ldsm2t(bh0, bh1, vh_b + off);
                        ldsm2t(bl0, bl1, vl_b + off);
                        mma_bf16(o[v], ph[j2], bh0, bh1);
                        mma_bf16(o[v], pl[j2], bh0, bh1);
                        mma_bf16(o[v], ph[j2], bl0, bl1);
                    }
                }
            }
        } else {
            // ---- RNG warps: mask for tile kt+1 (pure alu stream) ----
            if (kt < 63) {
                uint32_t mbv = 0u;
                const uint32_t cb = (uint32_t)((kt + 1) * 64 + 2 * tg);
                uint32_t f0 = r0f + cb;
                uint32_t f1 = r1f + cb;
#pragma unroll 2
                for (int t = 0; t < 8; ++t) {
                    uint32_t k0 = tf_bits(f0)      < T9 ? 1u : 0u;
                    uint32_t k1 = tf_bits(f0 + 1u) < T9 ? 1u : 0u;
                    uint32_t k2 = tf_bits(f1)      < T9 ? 1u : 0u;
                    uint32_t k3 = tf_bits(f1 + 1u) < T9 ? 1u : 0u;
                    mbv |= (k0 | (k1 << 1) | (k2 << 2) | (k3 << 3)) << (4 * t);
                    f0 += 8u; f1 += 8u;
                }
                sts32(mkb + (uint32_t)((kt + 1) & 1) * 512u + mt * 4, mbv);
            }
        }
    }

    // ---- epilogue (MMA warps only): quad-reduce l, scale, store ----
    if (is_mma) {
        lsum0 += __shfl_xor_sync(0xffffffffu, lsum0, 1);
        lsum0 += __shfl_xor_sync(0xffffffffu, lsum0, 2);
        lsum1 += __shfl_xor_sync(0xffffffffu, lsum1, 1);
        lsum1 += __shfl_xor_sync(0xffffffffu, lsum1, 2);
        const float sc0 = inv_keep / lsum0;
        const float sc1 = inv_keep / lsum1;
#pragma unroll
        for (int v = 0; v < 8; ++v) {
            int c = v * 8 + 2 * tg;
            *(float2*)(Og + (size_t)qr0 * 64 + c) = make_float2(o[v][0] * sc0, o[v][1] * sc0);
            *(float2*)(Og + (size_t)qr1 * 64 + c) = make_float2(o[v][2] * sc1, o[v][3] * sc1);
        }
    }
}

extern "C" void kernel_launch(void* const* d_in, const int* in_sizes, int n_in,
                              void* d_out, int out_size) {
    (void)in_sizes; (void)n_in; (void)out_size;
    const float* Q = (const float*)d_in[0];
    const float* K = (const float*)d_in[1];
    const float* V = (const float*)d_in[2];
    cudaFuncSetAttribute(fused_attn, cudaFuncAttributeMaxDynamicSharedMemorySize, 66560);
    prep_kv<<<2048, 256>>>(K, V);
    fused_attn<<<dim3(S_LEN / 64, NB), 256, 66560>>>(
        Q, (const float*)d_in[3], (const float*)d_in[4], (float*)d_out);
}